// round 1
// baseline (speedup 1.0000x reference)
#include <cuda_runtime.h>
#include <math.h>

// ModifiedChamferLoss: H=W=M=512, N=H*W=262144
// inputs: d_in[0]=prob_map [262144] f32, d_in[1]=gt [512,2] f32,
//         d_in[2]=all_img_locations (recomputed from index instead)
// output: scalar f32

#define NPIX  262144
#define MPTS  512
#define TPB   256
#define NBLK  (NPIX / TPB)

#define EPSF        1e-6f
#define MAXD_F      724.07733f          /* sqrtf(512^2+512^2) in fp32 */
#define MAXD2_F     524288.0f
#define EPS_OVER_MD 1.3810683e-9f       /* 1e-6f / 724.07733f in fp32 */

__device__ float g_sum_pd;      // sum over pixels of p * min_j d
__device__ float g_sum_p;       // sum p
__device__ int   g_min2[MPTS];  // per-GT min of candidate^2 (float bits, nonneg -> int order == float order)

__global__ void chamfer_init()
{
    int i = blockIdx.x * blockDim.x + threadIdx.x;
    if (i < MPTS) g_min2[i] = __float_as_int(MAXD2_F);
    if (i == 0) { g_sum_pd = 0.0f; g_sum_p = 0.0f; }
}

__global__ void __launch_bounds__(TPB)
chamfer_main(const float* __restrict__ prob, const float* __restrict__ gt)
{
    __shared__ float2 s_gt[MPTS];
    __shared__ int    s_min2[MPTS];

    const int tid = threadIdx.x;

    for (int j = tid; j < MPTS; j += TPB) {
        s_gt[j]   = reinterpret_cast<const float2*>(gt)[j];
        s_min2[j] = __float_as_int(MAXD2_F);
    }
    __syncthreads();

    const int   i  = blockIdx.x * TPB + tid;
    const float p  = prob[i];
    const float y  = (float)(i >> 9);     // row
    const float x  = (float)(i & 511);    // col
    const float p2 = p * p;
    const float p4 = p2 * p2;
    const float s  = 1.0f / (p4 + EPS_OVER_MD);
    const float s2 = s * s;

    float mind2 = 3.4e38f;

    #pragma unroll 8
    for (int j = 0; j < MPTS; ++j) {
        float2 g  = s_gt[j];
        float  dy = y - g.x;
        float  dx = x - g.y;
        float  d2 = fmaf(dy, dy, dx * dx);
        mind2 = fminf(mind2, d2);
        // prune: candidate = (sqrt(d2)+EPS)*s >= sqrt(d2)*s, so if d2*s2 >= cmin^2 it can't win.
        // stale s_min2 reads are safe (value only decreases).
        float t = d2 * s2;
        if (__float_as_int(t) < s_min2[j]) {
            float cand = fminf((sqrtf(d2) + EPSF) * s, MAXD_F); // clip-before-min == min-before-clip
            atomicMin(&s_min2[j], __float_as_int(cand * cand));
        }
    }

    // ---- term1 partial sums: sum p*min_d, sum p ----
    float v_pd = p * sqrtf(mind2);
    float v_p  = p;
    #pragma unroll
    for (int o = 16; o; o >>= 1) {
        v_pd += __shfl_down_sync(0xffffffffu, v_pd, o);
        v_p  += __shfl_down_sync(0xffffffffu, v_p,  o);
    }
    __shared__ float r_pd[TPB / 32], r_p[TPB / 32];
    const int lane = tid & 31, wid = tid >> 5;
    if (lane == 0) { r_pd[wid] = v_pd; r_p[wid] = v_p; }
    __syncthreads();   // also guarantees every thread finished its s_min2 atomics
    if (tid == 0) {
        float a = 0.0f, b = 0.0f;
        #pragma unroll
        for (int w = 0; w < TPB / 32; ++w) { a += r_pd[w]; b += r_p[w]; }
        atomicAdd(&g_sum_pd, a);
        atomicAdd(&g_sum_p,  b);
    }

    // ---- merge block-local column mins into global ----
    for (int j = tid; j < MPTS; j += TPB)
        atomicMin(&g_min2[j], s_min2[j]);
}

__global__ void __launch_bounds__(MPTS)
chamfer_finalize(float* __restrict__ out)
{
    const int tid = threadIdx.x;
    float cand = sqrtf(__int_as_float(g_min2[tid]));  // already clipped to [0, maxd]
    #pragma unroll
    for (int o = 16; o; o >>= 1)
        cand += __shfl_down_sync(0xffffffffu, cand, o);
    __shared__ float r[MPTS / 32];
    if ((tid & 31) == 0) r[tid >> 5] = cand;
    __syncthreads();
    if (tid == 0) {
        float t2 = 0.0f;
        #pragma unroll
        for (int w = 0; w < MPTS / 32; ++w) t2 += r[w];
        t2 *= (1.0f / (float)MPTS);                       // mean over GT points
        float term1 = g_sum_pd / (g_sum_p + EPSF);        // sum(p*min_d) / (n_est + eps)
        out[0] = term1 + t2;
    }
}

extern "C" void kernel_launch(void* const* d_in, const int* in_sizes, int n_in,
                              void* d_out, int out_size)
{
    const float* prob = (const float*)d_in[0];
    const float* gt   = (const float*)d_in[1];
    (void)in_sizes; (void)n_in; (void)out_size;

    chamfer_init<<<2, 256>>>();
    chamfer_main<<<NBLK, TPB>>>(prob, gt);
    chamfer_finalize<<<1, MPTS>>>((float*)d_out);
}

// round 2
// speedup vs baseline: 1.1506x; 1.1506x over previous
#include <cuda_runtime.h>
#include <math.h>

// ModifiedChamferLoss: H=W=M=512, N=H*W=262144
// d_in[0]=prob_map [262144] f32, d_in[1]=gt [512,2] f32 (d_in[2] unused; coords from index)
// out: scalar f32

#define NPIX  262144
#define MPTS  512
#define TPB   256
#define NBLK  (NPIX / TPB)

#define EPSF        1e-6f
#define MAXD_F      724.07733f          /* sqrt(512^2+512^2) */
#define MAXD2_F     524288.0f
#define EPS_OVER_MD 1.3810683e-9f       /* 1e-6f / 724.07733f */

__device__ float g_sum_pd;      // sum p * min_j d
__device__ float g_sum_p;       // sum p
__device__ int   g_min2[MPTS];  // per-GT min candidate^2 (float bits; nonneg -> int order == float order)

__global__ void chamfer_init()
{
    int i = blockIdx.x * blockDim.x + threadIdx.x;
    if (i < MPTS) g_min2[i] = __float_as_int(MAXD2_F);
    if (i == 0) { g_sum_pd = 0.0f; g_sum_p = 0.0f; }
}

__global__ void __launch_bounds__(TPB)
chamfer_main(const float* __restrict__ prob, const float* __restrict__ gt)
{
    __shared__ float2 s_ng[MPTS];    // NEGATED gt coords (saves a FADD->uses +)
    __shared__ int    s_min2[MPTS];

    const int tid  = threadIdx.x;
    const int lane = tid & 31;

    for (int j = tid; j < MPTS; j += TPB) {
        float2 g = reinterpret_cast<const float2*>(gt)[j];
        s_ng[j] = make_float2(-g.x, -g.y);
    }
    __syncthreads();

    const int   i  = blockIdx.x * TPB + tid;
    const float p  = prob[i];
    const float y  = (float)(i >> 9);     // row
    const float x  = (float)(i & 511);    // col
    const float p2 = p * p;
    const float p4 = p2 * p2;
    const float s  = 1.0f / (p4 + EPS_OVER_MD);
    const float s2 = s * s;

    // ---- seed: each thread seeds 2 columns with its own pixel's candidate (plain store) ----
    #pragma unroll
    for (int u = 0; u < 2; ++u) {
        int j = tid * 2 + u;
        float2 g  = s_ng[j];
        float  dy = y + g.x, dx = x + g.y;
        float  d2 = fmaf(dy, dy, dx * dx);
        float  cand = fminf((sqrtf(d2) + EPSF) * s, MAXD_F);
        s_min2[j] = __float_as_int(cand * cand);
    }
    __syncthreads();

    float mind2 = 3.4e38f;
    const int j0 = (tid >> 5) << 6;   // warp * 64 stagger (warp-uniform)

#define CH_BODY(J)                                                         \
    {                                                                      \
        float2 g  = s_ng[J];                                               \
        float  dy = y + g.x;                                               \
        float  dx = x + g.y;                                               \
        float  d2 = fmaf(dy, dy, dx * dx);                                 \
        mind2 = fminf(mind2, d2);                                          \
        /* prune: cand=(sqrt(d2)+EPS)*s >= sqrt(d2)*s, so d2*s2 >= cmin^2 => can't win */ \
        float  t  = d2 * s2;                                               \
        bool   pr = __float_as_int(t) < s_min2[J];                         \
        if (__any_sync(0xffffffffu, pr)) {                                 \
            float    cand = fminf((sqrtf(d2) + EPSF) * s, MAXD_F);         \
            unsigned c2   = __float_as_uint(cand * cand);                  \
            unsigned m    = __reduce_min_sync(0xffffffffu, c2);            \
            if (lane == 0) atomicMin(&s_min2[J], (int)m);                  \
        }                                                                  \
    }

    #pragma unroll 4
    for (int j = j0; j < MPTS; ++j) CH_BODY(j)
    #pragma unroll 4
    for (int j = 0; j < j0; ++j) CH_BODY(j)

#undef CH_BODY

    // ---- term1 partial sums ----
    float v_pd = p * sqrtf(mind2);
    float v_p  = p;
    #pragma unroll
    for (int o = 16; o; o >>= 1) {
        v_pd += __shfl_down_sync(0xffffffffu, v_pd, o);
        v_p  += __shfl_down_sync(0xffffffffu, v_p,  o);
    }
    __shared__ float r_pd[TPB / 32], r_p[TPB / 32];
    const int wid = tid >> 5;
    if (lane == 0) { r_pd[wid] = v_pd; r_p[wid] = v_p; }
    __syncthreads();   // also guarantees all s_min2 atomics in-block are done
    if (tid == 0) {
        float a = 0.0f, b = 0.0f;
        #pragma unroll
        for (int w = 0; w < TPB / 32; ++w) { a += r_pd[w]; b += r_p[w]; }
        atomicAdd(&g_sum_pd, a);
        atomicAdd(&g_sum_p,  b);
    }

    // ---- merge block-local column mins ----
    for (int j = tid; j < MPTS; j += TPB)
        atomicMin(&g_min2[j], s_min2[j]);
}

__global__ void __launch_bounds__(MPTS)
chamfer_finalize(float* __restrict__ out)
{
    const int tid = threadIdx.x;
    float cand = sqrtf(__int_as_float(g_min2[tid]));  // already clipped
    #pragma unroll
    for (int o = 16; o; o >>= 1)
        cand += __shfl_down_sync(0xffffffffu, cand, o);
    __shared__ float r[MPTS / 32];
    if ((tid & 31) == 0) r[tid >> 5] = cand;
    __syncthreads();
    if (tid == 0) {
        float t2 = 0.0f;
        #pragma unroll
        for (int w = 0; w < MPTS / 32; ++w) t2 += r[w];
        t2 *= (1.0f / (float)MPTS);
        float term1 = g_sum_pd / (g_sum_p + EPSF);
        out[0] = term1 + t2;
    }
}

extern "C" void kernel_launch(void* const* d_in, const int* in_sizes, int n_in,
                              void* d_out, int out_size)
{
    const float* prob = (const float*)d_in[0];
    const float* gt   = (const float*)d_in[1];
    (void)in_sizes; (void)n_in; (void)out_size;

    chamfer_init<<<2, 256>>>();
    chamfer_main<<<NBLK, TPB>>>(prob, gt);
    chamfer_finalize<<<1, MPTS>>>((float*)d_out);
}

// round 3
// speedup vs baseline: 1.9105x; 1.6604x over previous
#include <cuda_runtime.h>
#include <math.h>

// ModifiedChamferLoss: H=W=M=512, N=H*W=262144
// d_in[0]=prob_map [262144] f32, d_in[1]=gt [512,2] f32 (d_in[2] unused; coords from index)
// out: scalar f32

#define NPIX  262144
#define MPTS  512
#define NB1   256                 /* term1 blocks: 512 thr x 2 px */
#define NB2   512                 /* term2 blocks: 512 px each    */
#define TPB   512

#define EPSF        1e-6f
#define MAXD_F      724.07733f          /* sqrt(512^2+512^2) */
#define MAXD2_F     524288.0f
#define EPS_OVER_MD 1.3810683e-9f       /* 1e-6f / 724.07733f */

typedef unsigned long long ull;

__device__ __forceinline__ ull pk2(float lo, float hi) {
    ull r; asm("mov.b64 %0, {%1, %2};" : "=l"(r) : "f"(lo), "f"(hi)); return r;
}
#define UNPK2(a, b, v) asm("mov.b64 {%0, %1}, %2;" : "=f"(a), "=f"(b) : "l"(v))
__device__ __forceinline__ ull add2(ull a, ull b) {
    ull r; asm("add.rn.f32x2 %0, %1, %2;" : "=l"(r) : "l"(a), "l"(b)); return r;
}
__device__ __forceinline__ ull mul2(ull a, ull b) {
    ull r; asm("mul.rn.f32x2 %0, %1, %2;" : "=l"(r) : "l"(a), "l"(b)); return r;
}
__device__ __forceinline__ ull fma2(ull a, ull b, ull c) {
    ull r; asm("fma.rn.f32x2 %0, %1, %2, %3;" : "=l"(r) : "l"(a), "l"(b), "l"(c)); return r;
}

__device__ float g_sum_pd;      // sum p * min_j d
__device__ float g_sum_p;       // sum p
__device__ int   g_min2[MPTS];  // per-GT min candidate^2 (float bits; nonneg -> int order == float order)

__global__ void chamfer_init()
{
    int i = blockIdx.x * blockDim.x + threadIdx.x;
    if (i < MPTS) g_min2[i] = __float_as_int(MAXD2_F);
    if (i == 0) { g_sum_pd = 0.0f; g_sum_p = 0.0f; }
}

__global__ void __launch_bounds__(TPB)
chamfer_main(const float* __restrict__ prob, const float* __restrict__ gt)
{
    const int tid  = threadIdx.x;
    const int lane = tid & 31;
    const int wid  = tid >> 5;

    if (blockIdx.x < NB1) {
        // ================= term1: per-pixel min distance (row min) =================
        __shared__ __align__(16) float sgy[MPTS];
        __shared__ __align__(16) float sgx[MPTS];
        __shared__ float r_pd[TPB / 32], r_p[TPB / 32];

        {   // stage GT coords SoA
            float2 g = reinterpret_cast<const float2*>(gt)[tid];
            sgy[tid] = g.x; sgx[tid] = g.y;
        }
        __syncthreads();

        const int   i0 = blockIdx.x * (2 * TPB) + tid;   // pixel 0
        const int   i1 = i0 + TPB;                        // pixel 1
        const float p0 = prob[i0], p1 = prob[i1];

        const ull nyy0 = pk2(-(float)(i0 >> 9), -(float)(i0 >> 9));
        const ull nxx0 = pk2(-(float)(i0 & 511), -(float)(i0 & 511));
        const ull nyy1 = pk2(-(float)(i1 >> 9), -(float)(i1 >> 9));
        const ull nxx1 = pk2(-(float)(i1 & 511), -(float)(i1 & 511));

        float ma0 = 3.4e38f, mb0 = 3.4e38f, ma1 = 3.4e38f, mb1 = 3.4e38f;

        #pragma unroll 8
        for (int j = 0; j < MPTS; j += 2) {
            ull gyv = *reinterpret_cast<const ull*>(&sgy[j]);
            ull gxv = *reinterpret_cast<const ull*>(&sgx[j]);
            {   // pixel 0
                ull dy = add2(gyv, nyy0);
                ull dx = add2(gxv, nxx0);
                ull d2 = fma2(dy, dy, mul2(dx, dx));
                float a, b; UNPK2(a, b, d2);
                ma0 = fminf(ma0, a); mb0 = fminf(mb0, b);
            }
            {   // pixel 1
                ull dy = add2(gyv, nyy1);
                ull dx = add2(gxv, nxx1);
                ull d2 = fma2(dy, dy, mul2(dx, dx));
                float a, b; UNPK2(a, b, d2);
                ma1 = fminf(ma1, a); mb1 = fminf(mb1, b);
            }
        }

        float v_pd = p0 * sqrtf(fminf(ma0, mb0)) + p1 * sqrtf(fminf(ma1, mb1));
        float v_p  = p0 + p1;
        #pragma unroll
        for (int o = 16; o; o >>= 1) {
            v_pd += __shfl_down_sync(0xffffffffu, v_pd, o);
            v_p  += __shfl_down_sync(0xffffffffu, v_p,  o);
        }
        if (lane == 0) { r_pd[wid] = v_pd; r_p[wid] = v_p; }
        __syncthreads();
        if (tid == 0) {
            float a = 0.0f, b = 0.0f;
            #pragma unroll
            for (int w = 0; w < TPB / 32; ++w) { a += r_pd[w]; b += r_p[w]; }
            atomicAdd(&g_sum_pd, a);
            atomicAdd(&g_sum_p,  b);
        }
    } else {
        // ========== term2: per-GT min of (d+EPS)/(p^4+eps') (column min) ==========
        // Thread owns one GT column; cmin^2 lives in a register. Pixels staged in smem.
        __shared__ __align__(16) float sy[TPB];
        __shared__ __align__(16) float sx[TPB];
        __shared__ __align__(16) float ss[TPB];   // s  = 1/(p^4+eps')
        __shared__ __align__(16) float ss2[TPB];  // s^2

        const int b2 = blockIdx.x - NB1;
        {   // stage this block's pixel tile
            int   i  = b2 * TPB + tid;
            float p  = prob[i];
            float p2 = p * p;
            float s  = 1.0f / (p2 * p2 + EPS_OVER_MD);
            sy[tid]  = (float)(i >> 9);
            sx[tid]  = (float)(i & 511);
            ss[tid]  = s;
            ss2[tid] = s * s;
        }
        float2 g = reinterpret_cast<const float2*>(gt)[tid];   // my column
        const float gy = g.x, gx = g.y;
        const ull ngyy = pk2(-gy, -gy);
        const ull ngxx = pk2(-gx, -gx);
        __syncthreads();

        float cmin2 = MAXD2_F;

        #pragma unroll 2
        for (int c = 0; c < TPB; c += 8) {
            float tmin = 3.4e38f;
            #pragma unroll
            for (int u = 0; u < 8; u += 2) {
                ull yv  = *reinterpret_cast<const ull*>(&sy[c + u]);
                ull xv  = *reinterpret_cast<const ull*>(&sx[c + u]);
                ull s2v = *reinterpret_cast<const ull*>(&ss2[c + u]);
                ull dy  = add2(yv, ngyy);
                ull dx  = add2(xv, ngxx);
                ull d2  = fma2(dy, dy, mul2(dx, dx));
                ull tv  = mul2(d2, s2v);
                float t0, t1; UNPK2(t0, t1, tv);
                tmin = fminf(tmin, fminf(t0, t1));
            }
            // t = d2*s2 <= cand^2 (cand adds +EPS before scaling, then clips),
            // so tmin >= cmin2 proves no pixel in this chunk can improve.
            if (tmin < cmin2) {
                #pragma unroll
                for (int u = 0; u < 8; ++u) {
                    int   k  = c + u;
                    float dy = sy[k] - gy;
                    float dx = sx[k] - gx;
                    float d2 = fmaf(dy, dy, dx * dx);
                    float t  = d2 * ss2[k];
                    if (t < cmin2) {
                        float cand = fminf((sqrtf(d2) + EPSF) * ss[k], MAXD_F);
                        cmin2 = fminf(cmin2, cand * cand);
                    }
                }
            }
        }
        atomicMin(&g_min2[tid], __float_as_int(cmin2));
    }
}

__global__ void __launch_bounds__(MPTS)
chamfer_finalize(float* __restrict__ out)
{
    const int tid = threadIdx.x;
    float cand = sqrtf(__int_as_float(g_min2[tid]));  // already clipped to [0, maxd]
    #pragma unroll
    for (int o = 16; o; o >>= 1)
        cand += __shfl_down_sync(0xffffffffu, cand, o);
    __shared__ float r[MPTS / 32];
    if ((tid & 31) == 0) r[tid >> 5] = cand;
    __syncthreads();
    if (tid == 0) {
        float t2 = 0.0f;
        #pragma unroll
        for (int w = 0; w < MPTS / 32; ++w) t2 += r[w];
        t2 *= (1.0f / (float)MPTS);
        float term1 = g_sum_pd / (g_sum_p + EPSF);
        out[0] = term1 + t2;
    }
}

extern "C" void kernel_launch(void* const* d_in, const int* in_sizes, int n_in,
                              void* d_out, int out_size)
{
    const float* prob = (const float*)d_in[0];
    const float* gt   = (const float*)d_in[1];
    (void)in_sizes; (void)n_in; (void)out_size;

    chamfer_init<<<2, 256>>>();
    chamfer_main<<<NB1 + NB2, TPB>>>(prob, gt);
    chamfer_finalize<<<1, MPTS>>>((float*)d_out);
}

// round 4
// speedup vs baseline: 3.5274x; 1.8463x over previous
#include <cuda_runtime.h>
#include <math.h>

// ModifiedChamferLoss: H=W=M=512, N=H*W=262144
// d_in[0]=prob_map [262144] f32, d_in[1]=gt [512,2] f32 (d_in[2] unused; coords from index)
// out: scalar f32

#define NPIX  262144
#define MPTS  512
#define NB2   512                 /* term2 blocks: one image row each       */
#define NB1   256                 /* term1 blocks: one 32x32 pixel tile each */
#define TPB   512
#define FULLM 0xffffffffu

#define EPSF        1e-6f
#define MAXD_F      724.07733f          /* sqrt(512^2+512^2) */
#define MAXD2_F     524288.0f
#define MAXD2_BITS  0x49000000          /* __float_as_int(524288.0f) */
#define EPS_OVER_MD 1.3810683e-9f       /* 1e-6f / 724.07733f */

typedef unsigned long long ull;

__device__ __forceinline__ ull pk2(float lo, float hi) {
    ull r; asm("mov.b64 %0, {%1, %2};" : "=l"(r) : "f"(lo), "f"(hi)); return r;
}
#define UNPK2(a, b, v) asm("mov.b64 {%0, %1}, %2;" : "=f"(a), "=f"(b) : "l"(v))
__device__ __forceinline__ ull add2(ull a, ull b) {
    ull r; asm("add.rn.f32x2 %0, %1, %2;" : "=l"(r) : "l"(a), "l"(b)); return r;
}
__device__ __forceinline__ ull mul2(ull a, ull b) {
    ull r; asm("mul.rn.f32x2 %0, %1, %2;" : "=l"(r) : "l"(a), "l"(b)); return r;
}
__device__ __forceinline__ ull fma2(ull a, ull b, ull c) {
    ull r; asm("fma.rn.f32x2 %0, %1, %2, %3;" : "=l"(r) : "l"(a), "l"(b), "l"(c)); return r;
}

__device__ float g_sum_pd;      // sum p * min_j d
__device__ float g_sum_p;       // sum p
__device__ int   g_min2[MPTS];  // per-GT min candidate^2 (float bits; nonneg -> int order == float order)
__device__ float g_sgy[MPTS];   // gt y, sorted by gx ascending
__device__ float g_sgx[MPTS];   // gt x, sorted ascending

// prep: init accumulators + rank-sort GT by x (term2's mean is permutation-invariant)
__global__ void __launch_bounds__(1024) chamfer_prep(const float* __restrict__ gt)
{
    __shared__ float sgx[MPTS], sgy[MPTS];
    __shared__ int   srank[MPTS];
    const int t = threadIdx.x;
    if (t < MPTS) {
        float2 g = ((const float2*)gt)[t];
        sgy[t] = g.x; sgx[t] = g.y;
        srank[t] = 0;
        g_min2[t] = MAXD2_BITS;
    }
    if (t == 0) { g_sum_pd = 0.0f; g_sum_p = 0.0f; }
    __syncthreads();
    const int   j  = t >> 1;
    const float gx = sgx[j];
    const int   k0 = (t & 1) << 8;
    int cnt = 0;
    #pragma unroll 8
    for (int k = k0; k < k0 + 256; ++k) {
        float o = sgx[k];
        cnt += (o < gx) || (o == gx && k < j);
    }
    atomicAdd(&srank[j], cnt);
    __syncthreads();
    if (t < MPTS) {
        int r = srank[t];
        g_sgy[r] = sgy[t];
        g_sgx[r] = sgx[t];
    }
}

__global__ void __launch_bounds__(TPB)
chamfer_main(const float* __restrict__ prob, const float* __restrict__ gt)
{
    const int tid  = threadIdx.x;
    const int lane = tid & 31;
    const int wid  = tid >> 5;

    if (blockIdx.x < NB2) {
        // ========== term2: block = one image row; thread = one GT column ==========
        __shared__ __align__(16) float ss[TPB];    // s  = 1/(p^4+eps')
        __shared__ __align__(16) float ss2[TPB];   // s^2
        __shared__ float s_c2min[TPB / 8];         // per-8px-chunk min of s^2
        __shared__ float s_rowmin;                 // row min of s^2

        const int row = blockIdx.x;
        {
            float p  = prob[row * 512 + tid];
            float p2 = p * p;
            float s  = 1.0f / (p2 * p2 + EPS_OVER_MD);
            ss[tid]  = s;
            ss2[tid] = s * s;
        }
        __syncthreads();
        if (tid < 64) {
            float m = ss2[tid * 8];
            #pragma unroll
            for (int u = 1; u < 8; ++u) m = fminf(m, ss2[tid * 8 + u]);
            s_c2min[tid] = m;
        }
        __syncthreads();
        if (tid < 32) {
            float m = fminf(s_c2min[tid], s_c2min[tid + 32]);
            #pragma unroll
            for (int o = 16; o; o >>= 1) m = fminf(m, __shfl_down_sync(FULLM, m, o));
            if (tid == 0) s_rowmin = m;
        }
        __syncthreads();

        const float gy  = g_sgy[tid];
        const float gx  = g_sgx[tid];
        const float dy  = (float)row - gy;
        const float dy2 = dy * dy;

        const float seed  = __int_as_float(*((volatile int*)&g_min2[tid])); // achieved upper bound (or MAXD2)
        float       cmin2 = seed;

        // row-level lower bound: all candidates in this row have cand^2 >= dy2*s2min_row
        if (dy2 * s_rowmin < cmin2) {
            // warp-uniform wrap-around start (lanes' gx are adjacent after sort)
            int start = __float2int_rz(__shfl_sync(FULLM, gx, 0)) >> 3;
            const ull dy2v = pk2(dy2, dy2);
            const ull two2 = pk2(2.0f, 2.0f);

            for (int cc = 0; cc < 64; ++cc) {
                int   c    = (start + cc) & 63;
                float xm   = (float)(c << 3) - gx;                       // x0 - gx
                float dxlb = fmaxf(fmaxf(-xm - 7.0f, xm), 0.0f);
                float d2lb = fmaf(dxlb, dxlb, dy2);
                if (d2lb * s_c2min[c] < cmin2) {
                    ull   dxv  = pk2(xm, xm + 1.0f);
                    float tmin = 3.4e38f;
                    #pragma unroll
                    for (int u = 0; u < 8; u += 2) {
                        ull s2v = *(const ull*)&ss2[(c << 3) + u];
                        ull d2v = fma2(dxv, dxv, dy2v);
                        ull tv  = mul2(d2v, s2v);
                        float t0, t1; UNPK2(t0, t1, tv);
                        tmin = fminf(tmin, fminf(t0, t1));
                        dxv  = add2(dxv, two2);
                    }
                    // t = d2*s2 <= cand^2, so tmin >= cmin2 proves no win in chunk
                    if (tmin < cmin2) {
                        #pragma unroll
                        for (int u = 0; u < 8; ++u) {
                            int   k  = (c << 3) + u;
                            float dx = (float)k - gx;
                            float d2 = fmaf(dx, dx, dy2);
                            if (d2 * ss2[k] < cmin2) {
                                float cand = fminf((sqrtf(d2) + EPSF) * ss[k], MAXD_F);
                                cmin2 = fminf(cmin2, cand * cand);
                            }
                        }
                    }
                }
                if ((cc & 15) == 15)  // refresh from global running min
                    cmin2 = fminf(cmin2, __int_as_float(*((volatile int*)&g_min2[tid])));
            }
        }
        if (cmin2 < seed)
            atomicMin(&g_min2[tid], __float_as_int(cmin2));
    } else {
        // ========== term1: block = 32x32 pixel tile; GT candidates pruned by triangle ineq ==========
        __shared__ __align__(16) float s_cgy[MPTS + 2];   // negated, compacted
        __shared__ __align__(16) float s_cgx[MPTS + 2];
        __shared__ float s_wred[16];
        __shared__ int   s_wcnt[16];
        __shared__ float r_pd[TPB / 32], r_p[TPB / 32];

        const int b1  = blockIdx.x - NB2;
        const int ty0 = (b1 >> 4) << 5;
        const int tx0 = (b1 & 15) << 5;
        const float cy = (float)ty0 + 15.5f, cx = (float)tx0 + 15.5f;

        // phase A: candidate selection. keep g iff d(c,g) <= dmin_c + 2*r_tile (+slack)
        float2 g   = ((const float2*)gt)[tid];
        float  dyc = cy - g.x, dxc = cx - g.y;
        float  dc  = sqrtf(fmaf(dyc, dyc, dxc * dxc));

        float m = dc;
        #pragma unroll
        for (int o = 16; o; o >>= 1) m = fminf(m, __shfl_down_sync(FULLM, m, o));
        if (lane == 0) s_wred[wid] = m;
        __syncthreads();
        float dmin = s_wred[0];
        #pragma unroll
        for (int w = 1; w < 16; ++w) dmin = fminf(dmin, s_wred[w]);

        bool     keep = dc <= dmin + 44.3407f;   // 2*21.9203 (tile radius) + 0.5 slack
        unsigned bal  = __ballot_sync(FULLM, keep);
        if (lane == 0) s_wcnt[wid] = __popc(bal);
        __syncthreads();
        int base = 0, ncand = 0;
        #pragma unroll
        for (int w = 0; w < 16; ++w) { int cw = s_wcnt[w]; ncand += cw; if (w < wid) base += cw; }
        if (keep) {
            int pos = base + __popc(bal & ((1u << lane) - 1u));
            s_cgy[pos] = -g.x;
            s_cgx[pos] = -g.y;
        }
        __syncthreads();
        if (tid == 0 && (ncand & 1)) { s_cgy[ncand] = s_cgy[ncand - 1]; s_cgx[ncand] = s_cgx[ncand - 1]; }
        const int np = (ncand + 1) & ~1;
        __syncthreads();

        // phase B: 2 vertically-aligned pixels per thread (shared dx^2), 2 candidates per step
        const int y0i = ty0 + (tid >> 5), x0i = tx0 + (tid & 31);
        const int i0  = y0i * 512 + x0i;
        const int i1  = i0 + 16 * 512;
        const float p0 = prob[i0], p1 = prob[i1];

        const ull yy0 = pk2((float)y0i, (float)y0i);
        const ull yy1 = pk2((float)(y0i + 16), (float)(y0i + 16));
        const ull xx0 = pk2((float)x0i, (float)x0i);

        float ma0 = 3.4e38f, mb0 = 3.4e38f, ma1 = 3.4e38f, mb1 = 3.4e38f;
        #pragma unroll 2
        for (int j = 0; j < np; j += 2) {
            ull gyv = *(const ull*)&s_cgy[j];
            ull gxv = *(const ull*)&s_cgx[j];
            ull dxv = add2(gxv, xx0);
            ull dxx = mul2(dxv, dxv);
            {
                ull dyv = add2(gyv, yy0);
                ull d2  = fma2(dyv, dyv, dxx);
                float a, b; UNPK2(a, b, d2);
                ma0 = fminf(ma0, a); mb0 = fminf(mb0, b);
            }
            {
                ull dyv = add2(gyv, yy1);
                ull d2  = fma2(dyv, dyv, dxx);
                float a, b; UNPK2(a, b, d2);
                ma1 = fminf(ma1, a); mb1 = fminf(mb1, b);
            }
        }

        float v_pd = p0 * sqrtf(fminf(ma0, mb0)) + p1 * sqrtf(fminf(ma1, mb1));
        float v_p  = p0 + p1;
        #pragma unroll
        for (int o = 16; o; o >>= 1) {
            v_pd += __shfl_down_sync(FULLM, v_pd, o);
            v_p  += __shfl_down_sync(FULLM, v_p,  o);
        }
        if (lane == 0) { r_pd[wid] = v_pd; r_p[wid] = v_p; }
        __syncthreads();
        if (tid == 0) {
            float a = 0.0f, b = 0.0f;
            #pragma unroll
            for (int w = 0; w < TPB / 32; ++w) { a += r_pd[w]; b += r_p[w]; }
            atomicAdd(&g_sum_pd, a);
            atomicAdd(&g_sum_p,  b);
        }
    }
}

__global__ void __launch_bounds__(MPTS)
chamfer_finalize(float* __restrict__ out)
{
    const int tid = threadIdx.x;
    float cand = sqrtf(__int_as_float(g_min2[tid]));  // already clipped to [0, maxd]
    #pragma unroll
    for (int o = 16; o; o >>= 1)
        cand += __shfl_down_sync(FULLM, cand, o);
    __shared__ float r[MPTS / 32];
    if ((tid & 31) == 0) r[tid >> 5] = cand;
    __syncthreads();
    if (tid == 0) {
        float t2 = 0.0f;
        #pragma unroll
        for (int w = 0; w < MPTS / 32; ++w) t2 += r[w];
        t2 *= (1.0f / (float)MPTS);
        float term1 = g_sum_pd / (g_sum_p + EPSF);
        out[0] = term1 + t2;
    }
}

extern "C" void kernel_launch(void* const* d_in, const int* in_sizes, int n_in,
                              void* d_out, int out_size)
{
    const float* prob = (const float*)d_in[0];
    const float* gt   = (const float*)d_in[1];
    (void)in_sizes; (void)n_in; (void)out_size;

    chamfer_prep<<<1, 1024>>>(gt);
    chamfer_main<<<NB1 + NB2, TPB>>>(prob, gt);
    chamfer_finalize<<<1, MPTS>>>((float*)d_out);
}

// round 5
// speedup vs baseline: 4.6803x; 1.3268x over previous
#include <cuda_runtime.h>
#include <math.h>

// ModifiedChamferLoss: H=W=M=512, N=H*W=262144
// d_in[0]=prob_map [262144] f32, d_in[1]=gt [512,2] f32 (d_in[2] unused; coords from index)
// out: scalar f32

#define NPIX  262144
#define MPTS  512
#define NB2   512                 /* term2 blocks: one image row each        */
#define NB1   256                 /* term1 blocks: one 32x32 pixel tile each */
#define TPB   512
#define FULLM 0xffffffffu

#define EPSF        1e-6f
#define MAXD_F      724.07733f          /* sqrt(512^2+512^2) */
#define MAXD2_F     524288.0f
#define MAXD2_BITS  0x49000000          /* __float_as_int(524288.0f) */
#define EPS_OVER_MD 1.3810683e-9f       /* 1e-6f / 724.07733f */

typedef unsigned long long ull;

__device__ __forceinline__ ull pk2(float lo, float hi) {
    ull r; asm("mov.b64 %0, {%1, %2};" : "=l"(r) : "f"(lo), "f"(hi)); return r;
}
#define UNPK2(a, b, v) asm("mov.b64 {%0, %1}, %2;" : "=f"(a), "=f"(b) : "l"(v))
__device__ __forceinline__ ull add2(ull a, ull b) {
    ull r; asm("add.rn.f32x2 %0, %1, %2;" : "=l"(r) : "l"(a), "l"(b)); return r;
}
__device__ __forceinline__ ull mul2(ull a, ull b) {
    ull r; asm("mul.rn.f32x2 %0, %1, %2;" : "=l"(r) : "l"(a), "l"(b)); return r;
}
__device__ __forceinline__ ull fma2(ull a, ull b, ull c) {
    ull r; asm("fma.rn.f32x2 %0, %1, %2, %3;" : "=l"(r) : "l"(a), "l"(b), "l"(c)); return r;
}

__device__ float g_sum_pd;      // sum p * min_j d
__device__ float g_sum_p;       // sum p
__device__ int   g_min2[MPTS];  // per-GT min candidate^2, ORIGINAL gt order (float bits)
__device__ float g_sgy[MPTS];   // gt y, sorted by gx ascending
__device__ float g_sgx[MPTS];   // gt x, sorted ascending
__device__ int   g_sidx[MPTS];  // sorted position -> original index

// prep (16 blocks): blocks 0-7 rank-sort GT by x; blocks 8-15 seed g_min2 with
// exact candidates from the 64 pixels nearest each GT point (achieved upper bounds).
__global__ void __launch_bounds__(TPB)
chamfer_prep(const float* __restrict__ prob, const float* __restrict__ gt)
{
    const int b = blockIdx.x;
    const int t = threadIdx.x;

    if (b < 8) {
        __shared__ float sgx[MPTS], sgy[MPTS];
        __shared__ int   srank[64];
        {
            float2 g = ((const float2*)gt)[t];
            sgy[t] = g.x; sgx[t] = g.y;
        }
        if (t < 64) srank[t] = 0;
        if (b == 0 && t == 0) { g_sum_pd = 0.0f; g_sum_p = 0.0f; }
        __syncthreads();

        const int   j  = (b << 6) + (t >> 3);     // this block's 64 GT points
        const float gx = sgx[j];
        const int   k0 = (t & 7) << 6;            // 8 threads cover 512 in 64-slices
        int cnt = 0;
        #pragma unroll 8
        for (int k = k0; k < k0 + 64; ++k) {
            float o = sgx[k];
            cnt += (o < gx) || (o == gx && k < j);
        }
        atomicAdd(&srank[t >> 3], cnt);
        __syncthreads();
        if ((t & 7) == 0) {
            int r = srank[t >> 3];
            g_sgy[r]  = sgy[j];
            g_sgx[r]  = sgx[j];
            g_sidx[r] = j;
        }
    } else {
        // seed: GT j scanned by 8 threads x 8 pixels in its nearest row, gx +/- 32
        const int j = ((b - 8) << 6) + (t >> 3);
        float2 g = ((const float2*)gt)[j];
        const float gy = g.x, gx = g.y;
        const int row = min(max(__float2int_rn(gy), 0), 511);
        const int cb  = min(max(__float2int_rn(gx) - 32, 0), 448);
        const int c0  = cb + ((t & 7) << 3);
        const float dy  = (float)row - gy;
        const float dy2 = dy * dy;

        float best = MAXD2_F;
        #pragma unroll
        for (int u = 0; u < 8; ++u) {
            int   c  = c0 + u;
            float p  = prob[row * 512 + c];
            float p2 = p * p;
            float s  = 1.0f / (p2 * p2 + EPS_OVER_MD);
            float dx = (float)c - gx;
            float d2 = fmaf(dx, dx, dy2);
            float cand = fminf((sqrtf(d2) + EPSF) * s, MAXD_F);
            best = fminf(best, cand * cand);
        }
        #pragma unroll
        for (int o = 4; o; o >>= 1)
            best = fminf(best, __shfl_down_sync(FULLM, best, o, 8));
        if ((t & 7) == 0) g_min2[j] = __float_as_int(best);
    }
}

__global__ void __launch_bounds__(TPB)
chamfer_main(const float* __restrict__ prob, const float* __restrict__ gt)
{
    const int tid  = threadIdx.x;
    const int lane = tid & 31;
    const int wid  = tid >> 5;

    if (blockIdx.x < NB2) {
        // ========== term2: block = one image row; thread = one GT column ==========
        __shared__ __align__(16) float ss[TPB];    // s  = 1/(p^4+eps')
        __shared__ __align__(16) float ss2[TPB];   // s^2
        __shared__ float s_c2min[TPB / 8];         // per-8px-chunk min of s^2
        __shared__ float s_rowmin;                 // row min of s^2

        const int row = blockIdx.x;
        {
            float p  = prob[row * 512 + tid];
            float p2 = p * p;
            float s  = 1.0f / (p2 * p2 + EPS_OVER_MD);
            ss[tid]  = s;
            ss2[tid] = s * s;
        }
        __syncthreads();
        if (tid < 64) {
            float m = ss2[tid * 8];
            #pragma unroll
            for (int u = 1; u < 8; ++u) m = fminf(m, ss2[tid * 8 + u]);
            s_c2min[tid] = m;
        }
        __syncthreads();
        if (tid < 32) {
            float m = fminf(s_c2min[tid], s_c2min[tid + 32]);
            #pragma unroll
            for (int o = 16; o; o >>= 1) m = fminf(m, __shfl_down_sync(FULLM, m, o));
            if (tid == 0) s_rowmin = m;
        }
        __syncthreads();

        const float gy  = g_sgy[tid];
        const float gx  = g_sgx[tid];
        const int   idx = g_sidx[tid];              // original index for g_min2
        const float dy  = (float)row - gy;
        const float dy2 = dy * dy;

        const float seed  = __int_as_float(*((volatile int*)&g_min2[idx]));
        float       cmin2 = seed;

        // row-level lower bound: all candidates in this row have cand^2 >= dy2*s2min_row
        if (dy2 * s_rowmin < cmin2) {
            // warp-uniform wrap-around start (lanes' gx are adjacent after sort)
            int start = __float2int_rz(__shfl_sync(FULLM, gx, 0)) >> 3;
            const ull dy2v = pk2(dy2, dy2);
            const ull two2 = pk2(2.0f, 2.0f);

            for (int cc = 0; cc < 64; ++cc) {
                int   c    = (start + cc) & 63;
                float xm   = (float)(c << 3) - gx;                       // x0 - gx
                float dxlb = fmaxf(fmaxf(-xm - 7.0f, xm), 0.0f);
                float d2lb = fmaf(dxlb, dxlb, dy2);
                if (d2lb * s_c2min[c] < cmin2) {
                    ull   dxv  = pk2(xm, xm + 1.0f);
                    float tmin = 3.4e38f;
                    #pragma unroll
                    for (int u = 0; u < 8; u += 2) {
                        ull s2v = *(const ull*)&ss2[(c << 3) + u];
                        ull d2v = fma2(dxv, dxv, dy2v);
                        ull tv  = mul2(d2v, s2v);
                        float t0, t1; UNPK2(t0, t1, tv);
                        tmin = fminf(tmin, fminf(t0, t1));
                        dxv  = add2(dxv, two2);
                    }
                    // t = d2*s2 <= cand^2, so tmin >= cmin2 proves no win in chunk
                    if (tmin < cmin2) {
                        #pragma unroll
                        for (int u = 0; u < 8; ++u) {
                            int   k  = (c << 3) + u;
                            float dx = (float)k - gx;
                            float d2 = fmaf(dx, dx, dy2);
                            if (d2 * ss2[k] < cmin2) {
                                float cand = fminf((sqrtf(d2) + EPSF) * ss[k], MAXD_F);
                                cmin2 = fminf(cmin2, cand * cand);
                            }
                        }
                    }
                }
                if ((cc & 15) == 15)  // refresh from global running min
                    cmin2 = fminf(cmin2, __int_as_float(*((volatile int*)&g_min2[idx])));
            }
        }
        if (cmin2 < seed)
            atomicMin(&g_min2[idx], __float_as_int(cmin2));
    } else {
        // ========== term1: block = 32x32 pixel tile; GT candidates pruned by triangle ineq ==========
        __shared__ __align__(16) float s_cgy[MPTS + 2];   // negated, compacted
        __shared__ __align__(16) float s_cgx[MPTS + 2];
        __shared__ float s_wred[16];
        __shared__ int   s_wcnt[16];
        __shared__ float r_pd[TPB / 32], r_p[TPB / 32];

        const int b1  = blockIdx.x - NB2;
        const int ty0 = (b1 >> 4) << 5;
        const int tx0 = (b1 & 15) << 5;
        const float cy = (float)ty0 + 15.5f, cx = (float)tx0 + 15.5f;

        // phase A: candidate selection. keep g iff d(c,g) <= dmin_c + 2*r_tile (+slack)
        float2 g   = ((const float2*)gt)[tid];
        float  dyc = cy - g.x, dxc = cx - g.y;
        float  dc  = sqrtf(fmaf(dyc, dyc, dxc * dxc));

        float m = dc;
        #pragma unroll
        for (int o = 16; o; o >>= 1) m = fminf(m, __shfl_down_sync(FULLM, m, o));
        if (lane == 0) s_wred[wid] = m;
        __syncthreads();
        float dmin = s_wred[0];
        #pragma unroll
        for (int w = 1; w < 16; ++w) dmin = fminf(dmin, s_wred[w]);

        bool     keep = dc <= dmin + 44.3407f;   // 2*21.9203 (tile radius) + 0.5 slack
        unsigned bal  = __ballot_sync(FULLM, keep);
        if (lane == 0) s_wcnt[wid] = __popc(bal);
        __syncthreads();
        int base = 0, ncand = 0;
        #pragma unroll
        for (int w = 0; w < 16; ++w) { int cw = s_wcnt[w]; ncand += cw; if (w < wid) base += cw; }
        if (keep) {
            int pos = base + __popc(bal & ((1u << lane) - 1u));
            s_cgy[pos] = -g.x;
            s_cgx[pos] = -g.y;
        }
        __syncthreads();
        if (tid == 0 && (ncand & 1)) { s_cgy[ncand] = s_cgy[ncand - 1]; s_cgx[ncand] = s_cgx[ncand - 1]; }
        const int np = (ncand + 1) & ~1;
        __syncthreads();

        // phase B: 2 vertically-aligned pixels per thread (shared dx^2), 2 candidates per step
        const int y0i = ty0 + (tid >> 5), x0i = tx0 + (tid & 31);
        const int i0  = y0i * 512 + x0i;
        const int i1  = i0 + 16 * 512;
        const float p0 = prob[i0], p1 = prob[i1];

        const ull yy0 = pk2((float)y0i, (float)y0i);
        const ull yy1 = pk2((float)(y0i + 16), (float)(y0i + 16));
        const ull xx0 = pk2((float)x0i, (float)x0i);

        float ma0 = 3.4e38f, mb0 = 3.4e38f, ma1 = 3.4e38f, mb1 = 3.4e38f;
        #pragma unroll 2
        for (int j = 0; j < np; j += 2) {
            ull gyv = *(const ull*)&s_cgy[j];
            ull gxv = *(const ull*)&s_cgx[j];
            ull dxv = add2(gxv, xx0);
            ull dxx = mul2(dxv, dxv);
            {
                ull dyv = add2(gyv, yy0);
                ull d2  = fma2(dyv, dyv, dxx);
                float a, b; UNPK2(a, b, d2);
                ma0 = fminf(ma0, a); mb0 = fminf(mb0, b);
            }
            {
                ull dyv = add2(gyv, yy1);
                ull d2  = fma2(dyv, dyv, dxx);
                float a, b; UNPK2(a, b, d2);
                ma1 = fminf(ma1, a); mb1 = fminf(mb1, b);
            }
        }

        float v_pd = p0 * sqrtf(fminf(ma0, mb0)) + p1 * sqrtf(fminf(ma1, mb1));
        float v_p  = p0 + p1;
        #pragma unroll
        for (int o = 16; o; o >>= 1) {
            v_pd += __shfl_down_sync(FULLM, v_pd, o);
            v_p  += __shfl_down_sync(FULLM, v_p,  o);
        }
        if (lane == 0) { r_pd[wid] = v_pd; r_p[wid] = v_p; }
        __syncthreads();
        if (tid == 0) {
            float a = 0.0f, b = 0.0f;
            #pragma unroll
            for (int w = 0; w < TPB / 32; ++w) { a += r_pd[w]; b += r_p[w]; }
            atomicAdd(&g_sum_pd, a);
            atomicAdd(&g_sum_p,  b);
        }
    }
}

__global__ void __launch_bounds__(MPTS)
chamfer_finalize(float* __restrict__ out)
{
    const int tid = threadIdx.x;
    float cand = sqrtf(__int_as_float(g_min2[tid]));  // already clipped to [0, maxd]
    #pragma unroll
    for (int o = 16; o; o >>= 1)
        cand += __shfl_down_sync(FULLM, cand, o);
    __shared__ float r[MPTS / 32];
    if ((tid & 31) == 0) r[tid >> 5] = cand;
    __syncthreads();
    if (tid == 0) {
        float t2 = 0.0f;
        #pragma unroll
        for (int w = 0; w < MPTS / 32; ++w) t2 += r[w];
        t2 *= (1.0f / (float)MPTS);
        float term1 = g_sum_pd / (g_sum_p + EPSF);
        out[0] = term1 + t2;
    }
}

extern "C" void kernel_launch(void* const* d_in, const int* in_sizes, int n_in,
                              void* d_out, int out_size)
{
    const float* prob = (const float*)d_in[0];
    const float* gt   = (const float*)d_in[1];
    (void)in_sizes; (void)n_in; (void)out_size;

    chamfer_prep<<<16, TPB>>>(prob, gt);
    chamfer_main<<<NB1 + NB2, TPB>>>(prob, gt);
    chamfer_finalize<<<1, MPTS>>>((float*)d_out);
}